// round 12
// baseline (speedup 1.0000x reference)
#include <cuda_runtime.h>
#include <cuda_bf16.h>
#include <cuda_fp16.h>
#include <math.h>
#include <stdint.h>

#define B_   2
#define S_   2048
#define D_   2048
#define H_   16
#define HD_  128
#define LY_  512
#define DY_  2048
#define HHD  2048   // H*HD

typedef __nv_bfloat16 bf16;
typedef __half fp16;

// ---------------- scratch (no allocations allowed) ----------------
__device__ float g_q  [B_*S_*HHD];
__device__ float g_k  [B_*S_*HHD];
__device__ float g_v  [B_*S_*HHD];
__device__ float g_yk [B_*LY_*HHD];
__device__ float g_yv [B_*LY_*HHD];
// bf16 hi/lo splits
__device__ bf16 g_xh [B_*S_*D_],   g_xl [B_*S_*D_];
__device__ bf16 g_yh [B_*LY_*DY_], g_yl [B_*LY_*DY_];
__device__ bf16 g_ath[B_*S_*HHD],  g_atl[B_*S_*HHD];
__device__ bf16 g_qh [B_*S_*HHD],  g_ql [B_*S_*HHD];
__device__ bf16 g_kh [B_*S_*HHD],  g_kl [B_*S_*HHD];
__device__ bf16 g_ykh[B_*LY_*HHD], g_ykl[B_*LY_*HHD];
// fp16 hi/lo transposed V: [b][h][hd][s]
__device__ fp16 g_vth [B_*H_*HD_*S_],  g_vtl [B_*H_*HD_*S_];
__device__ fp16 g_yvth[B_*H_*HD_*LY_], g_yvtl[B_*H_*HD_*LY_];
// transposed + hi/lo split weights [N][K] bf16
__device__ bf16 g_wqh [HHD*D_],  g_wql [HHD*D_];
__device__ bf16 g_wkh [HHD*D_],  g_wkl [HHD*D_];
__device__ bf16 g_wvh [HHD*D_],  g_wvl [HHD*D_];
__device__ bf16 g_woh [D_*HHD],  g_wol [D_*HHD];
__device__ bf16 g_wkyh[HHD*DY_], g_wkyl[HHD*DY_];
__device__ bf16 g_wvyh[HHD*DY_], g_wvyl[HHD*DY_];

// =====================================================================
// Generic helpers
// =====================================================================
__device__ __forceinline__ uint32_t smem_u32(const void* p) {
    uint32_t a;
    asm("{ .reg .u64 t; cvta.to.shared.u64 t, %1; cvt.u32.u64 %0, t; }"
        : "=r"(a) : "l"(p));
    return a;
}
#define MBARRIER_INIT(addr, cnt) \
    asm volatile("mbarrier.init.shared.b64 [%0], %1;" :: "r"(addr), "r"(cnt) : "memory")
#define MBARRIER_INVAL(addr) \
    asm volatile("mbarrier.inval.shared.b64 [%0];" :: "r"(addr) : "memory")

__device__ __forceinline__ void mbar_wait_parity(uint32_t mbar, uint32_t parity) {
    asm volatile(
        "{\n\t.reg .pred P1;\n\t"
        "WAIT_LOOP_%=:\n\t"
        "mbarrier.try_wait.parity.acquire.cta.shared::cta.b64 P1, [%0], %1, 0x989680;\n\t"
        "@P1 bra.uni WAIT_DONE_%=;\n\t"
        "bra.uni WAIT_LOOP_%=;\n\t"
        "WAIT_DONE_%=:\n\t}"
        :: "r"(mbar), "r"(parity) : "memory");
}

__device__ __forceinline__ uint32_t sw128(uint32_t off) {
    return off ^ ((off >> 3) & 0x70);
}

__device__ __forceinline__ void split_hl(float x, bf16& h, bf16& l) {
    h = __float2bfloat16_rn(x);
    l = __float2bfloat16_rn(x - __bfloat162float(h));
}
__device__ __forceinline__ void split_hl16(float x, fp16& h, fp16& l) {
    h = __float2half_rn(x);
    l = __float2half_rn(x - __half2float(h));
}

__device__ __forceinline__ uint32_t pack2(float lo, float hi) {
    __nv_bfloat162 t = __floats2bfloat162_rn(lo, hi);
    return *(uint32_t*)&t;
}

// =====================================================================
// tcgen05 helpers — arch-specific pass only
// =====================================================================
#if defined(__CUDA_ARCH_FEAT_SM103_ALL) || !defined(__CUDA_ARCH__)

__device__ __forceinline__ uint32_t elect_one() {
    uint32_t pred;
    asm volatile("{\n\t.reg .pred p;\n\telect.sync _|p, 0xFFFFFFFF;\n\t"
                 "selp.b32 %0, 1, 0, p;\n\t}" : "=r"(pred));
    return pred;
}
#define TCGEN05_ALLOC(smem_addr, ncols) \
    asm volatile("tcgen05.alloc.cta_group::1.sync.aligned.shared::cta.b32 [%0], %1;" \
                 :: "r"(smem_addr), "r"(ncols) : "memory")
#define TCGEN05_DEALLOC(tmem, ncols) \
    asm volatile("tcgen05.dealloc.cta_group::1.sync.aligned.b32 %0, %1;" :: "r"(tmem), "r"(ncols))
#define TCGEN05_RELINQ() \
    asm volatile("tcgen05.relinquish_alloc_permit.cta_group::1.sync.aligned;")
#define TCGEN05_COMMIT(mbar) \
    asm volatile("tcgen05.commit.cta_group::1.mbarrier::arrive::one.shared::cluster.b64 [%0];" \
                 :: "r"(mbar) : "memory")
#define TCGEN05_WAIT_LD() asm volatile("tcgen05.wait::ld.sync.aligned;" ::: "memory")
#define TCGEN05_FENCE_BEFORE() asm volatile("tcgen05.fence::before_thread_sync;" ::: "memory")
#define TCGEN05_FENCE_AFTER()  asm volatile("tcgen05.fence::after_thread_sync;" ::: "memory")
#define FENCE_ASYNC_SHARED() asm volatile("fence.proxy.async.shared::cta;" ::: "memory")

#define TCGEN05_LD_X32(r, tmem_addr) \
    asm volatile( \
        "tcgen05.ld.sync.aligned.32x32b.x32.b32 " \
        "{%0, %1, %2, %3, %4, %5, %6, %7, " \
        " %8, %9, %10, %11, %12, %13, %14, %15, " \
        " %16, %17, %18, %19, %20, %21, %22, %23, " \
        " %24, %25, %26, %27, %28, %29, %30, %31}, [%32];" \
        : "=r"((r)[0]),  "=r"((r)[1]),  "=r"((r)[2]),  "=r"((r)[3]), \
          "=r"((r)[4]),  "=r"((r)[5]),  "=r"((r)[6]),  "=r"((r)[7]), \
          "=r"((r)[8]),  "=r"((r)[9]),  "=r"((r)[10]), "=r"((r)[11]), \
          "=r"((r)[12]), "=r"((r)[13]), "=r"((r)[14]), "=r"((r)[15]), \
          "=r"((r)[16]), "=r"((r)[17]), "=r"((r)[18]), "=r"((r)[19]), \
          "=r"((r)[20]), "=r"((r)[21]), "=r"((r)[22]), "=r"((r)[23]), \
          "=r"((r)[24]), "=r"((r)[25]), "=r"((r)[26]), "=r"((r)[27]), \
          "=r"((r)[28]), "=r"((r)[29]), "=r"((r)[30]), "=r"((r)[31]) \
        : "r"(tmem_addr))

// SW128 K-major smem descriptor: layout=SW128(2), version=1, SBO=64, LBO=1
__device__ __forceinline__ uint64_t make_desc_sw128(uint32_t addr) {
    uint64_t d = (uint64_t(2) << 61) | (uint64_t(1) << 46)
               | (uint64_t(64) << 32) | (uint64_t(1) << 16);
    return d | ((uint64_t)(addr >> 4) & 0x3FFF);
}

// f16-kind SS MMA (bf16 or fp16 per idesc)
__device__ __forceinline__ void mma_f16_ss(uint32_t d_tmem, uint64_t a_desc,
                                           uint64_t b_desc, uint32_t idesc,
                                           uint32_t enable) {
    asm volatile(
        "{\n\t.reg .pred p;\n\tsetp.ne.u32 p, %5, 0;\n\t"
        "tcgen05.mma.cta_group::1.kind::f16 [%0], %1, %2, %3, {%4, %4, %4, %4}, p;\n\t}"
        :: "r"(d_tmem), "l"(a_desc), "l"(b_desc), "r"(idesc), "r"(0u), "r"(enable)
        : "memory");
}
#endif

// =====================================================================
// bf16x3 GEMM (R8/R11 form): C = (Ah+Al) @ (Bh+Bl)^T
// =====================================================================
#define GBM 128
#define GBN 256
#define GBK 64
#define STG_STRIDE 98304
#define OFF_AH 0
#define OFF_AL 16384
#define OFF_BH 32768
#define OFF_BL 65536
#define GSMEM (1024 + 2*STG_STRIDE)

#define BF16_IDESC ((1u<<4) | (1u<<7) | (1u<<10) | ((GBN/8)<<17) | ((GBM/16)<<24))

__global__ void __launch_bounds__(256, 1) bf16x3_gemm_kernel(
    const bf16* __restrict__ Ah, const bf16* __restrict__ Al,
    const bf16* __restrict__ Bh, const bf16* __restrict__ Bl,
    float* __restrict__ C, int M, int N, int K)
{
#if defined(__CUDA_ARCH_FEAT_SM103_ALL) || !defined(__CUDA_ARCH__)
    extern __shared__ char smem[];
    uint32_t sb = smem_u32(smem);
    int tid = threadIdx.x, wid = tid >> 5, lane = tid & 31;
    int bm0 = blockIdx.y * GBM, bn0 = blockIdx.x * GBN;

    if (wid == 0) TCGEN05_ALLOC(sb + 0, 256);
    if (tid == 0) {
        MBARRIER_INIT(sb + 8, 1);
        MBARRIER_INIT(sb + 16, 1);
        MBARRIER_INIT(sb + 24, 1);
    }
    __syncthreads();
    uint32_t tmem;
    asm volatile("ld.shared.b32 %0, [%1];" : "=r"(tmem) : "r"(sb + 0));
    if (wid == 0) TCGEN05_RELINQ();

    int ph0 = 0, ph1 = 0;
    const int niter = K / GBK;

    for (int i = 0; i < niter; i++) {
        int s = i & 1;
        uint32_t stg = 1024 + s * STG_STRIDE;
        if (i >= 2) {
            if (s == 0) { mbar_wait_parity(sb + 8,  ph0); ph0 ^= 1; }
            else        { mbar_wait_parity(sb + 16, ph1); ph1 ^= 1; }
        }
        int k0 = i * GBK;
        {
#pragma unroll
            for (int r = 0; r < 4; r++) {
                int e = tid + r * 256;
                int row = e >> 3;
                int ch = e & 7;
                size_t goff = (size_t)(bm0 + row) * K + k0 + ch * 8;
                uint32_t soff = sw128((uint32_t)(row * 128 + ch * 16));
                *(uint4*)(smem + stg + OFF_AH + soff) = *(const uint4*)(Ah + goff);
                *(uint4*)(smem + stg + OFF_AL + soff) = *(const uint4*)(Al + goff);
            }
        }
        {
#pragma unroll
            for (int r = 0; r < 8; r++) {
                int e = tid + r * 256;
                int row = e >> 3;
                int ch = e & 7;
                size_t goff = (size_t)(bn0 + row) * K + k0 + ch * 8;
                uint32_t soff = sw128((uint32_t)(row * 128 + ch * 16));
                *(uint4*)(smem + stg + OFF_BH + soff) = *(const uint4*)(Bh + goff);
                *(uint4*)(smem + stg + OFF_BL + soff) = *(const uint4*)(Bl + goff);
            }
        }
        __syncthreads();

        if (wid == 0) {
            FENCE_ASYNC_SHARED();
            if (elect_one()) {
                uint64_t ah = make_desc_sw128(sb + stg + OFF_AH);
                uint64_t al = make_desc_sw128(sb + stg + OFF_AL);
                uint64_t bh = make_desc_sw128(sb + stg + OFF_BH);
                uint64_t bl = make_desc_sw128(sb + stg + OFF_BL);
#pragma unroll
                for (int j = 0; j < 4; j++)
                    mma_f16_ss(tmem, ah + j * 2, bh + j * 2, BF16_IDESC,
                               (i > 0 || j > 0) ? 1u : 0u);
#pragma unroll
                for (int j = 0; j < 4; j++)
                    mma_f16_ss(tmem, ah + j * 2, bl + j * 2, BF16_IDESC, 1u);
#pragma unroll
                for (int j = 0; j < 4; j++)
                    mma_f16_ss(tmem, al + j * 2, bh + j * 2, BF16_IDESC, 1u);
                TCGEN05_COMMIT(sb + 8 + 8 * s);
            }
        }
    }

    __syncthreads();
    if (wid == 0 && elect_one()) TCGEN05_COMMIT(sb + 24);
    mbar_wait_parity(sb + 24, 0);
    TCGEN05_FENCE_AFTER();

    if (wid < 4) {
        float* crow = C + (size_t)(bm0 + wid * 32 + lane) * N + bn0;
#pragma unroll
        for (int c0 = 0; c0 < GBN; c0 += 32) {
            uint32_t r[32];
            TCGEN05_LD_X32(r, tmem + c0);
            TCGEN05_WAIT_LD();
#pragma unroll
            for (int j = 0; j < 32; j += 4) {
                *(float4*)(crow + c0 + j) = make_float4(
                    __uint_as_float(r[j]), __uint_as_float(r[j + 1]),
                    __uint_as_float(r[j + 2]), __uint_as_float(r[j + 3]));
            }
        }
    }
    __syncthreads();
    if (tid == 0) {
        MBARRIER_INVAL(sb + 8); MBARRIER_INVAL(sb + 16); MBARRIER_INVAL(sb + 24);
    }
    if (wid == 0) TCGEN05_DEALLOC(tmem, 256);
#endif
}

// =====================================================================
// Flash attention v2 (R8/R11 verbatim)
// TMEM: S 0-63 | O_self 64-191 | O_cross 192-319
// =====================================================================
#define AT_QH 1024
#define AT_QL (AT_QH + 32768)
#define AT_STG0 (AT_QL + 32768)
#define AT_SSTRIDE 65536
#define SO_KH 0
#define SO_KL 16384
#define SO_VH 32768
#define SO_VL 49152
#define AT_P  (AT_STG0 + 2*AT_SSTRIDE)
#define AT_SMEM (AT_P + 16384)

#define IDESC_S    ((1u<<4) | (1u<<7) | (1u<<10) | ((64/8)<<17)  | ((128/16)<<24))
#define IDESC_PV16 ((1u<<4) | (0u<<7) | (0u<<10) | ((128/8)<<17) | ((128/16)<<24))
#define EXP_SHIFT 6.0f

__global__ void __launch_bounds__(256, 1) fattn_kernel(
    const bf16* __restrict__ Qh_g, const bf16* __restrict__ Ql_g,
    const bf16* __restrict__ Kh_g, const bf16* __restrict__ Kl_g,
    const fp16* __restrict__ VTh_g, const fp16* __restrict__ VTl_g,
    const bf16* __restrict__ YKh_g, const bf16* __restrict__ YKl_g,
    const fp16* __restrict__ YVTh_g, const fp16* __restrict__ YVTl_g,
    const float* __restrict__ gate,
    bf16* __restrict__ Oh, bf16* __restrict__ Ol)
{
#if defined(__CUDA_ARCH_FEAT_SM103_ALL) || !defined(__CUDA_ARCH__)
    extern __shared__ char smem[];
    uint32_t sb = smem_u32(smem);
    int tid = threadIdx.x, wid = tid >> 5, lane = tid & 31;
    int qt = blockIdx.x, h = blockIdx.y, b = blockIdx.z;
    int s0 = qt * 128;
    int row = wid * 32 + lane;

    if (wid == 0) TCGEN05_ALLOC(sb + 0, 512);
    if (tid == 0) { MBARRIER_INIT(sb + 8, 1); MBARRIER_INIT(sb + 16, 1); }
    __syncthreads();
    uint32_t tmem;
    asm volatile("ld.shared.b32 %0, [%1];" : "=r"(tmem) : "r"(sb + 0));
    if (wid == 0) TCGEN05_RELINQ();

    // ---- load Q tile once ----
    {
#pragma unroll
        for (int r = 0; r < 8; r++) {
            int e = tid + r * 256;
            int qr = e >> 4;
            int ch = e & 15;
            size_t goff = (size_t)(b * S_ + s0 + qr) * HHD + h * HD_ + ch * 8;
            uint32_t byte = (uint32_t)((qr >> 3) * 1024 + (ch >> 3) * 16384
                                       + (qr & 7) * 128 + (ch & 7) * 16);
            uint32_t so = sw128(byte);
            *(uint4*)(smem + AT_QH + so) = *(const uint4*)(Qh_g + goff);
            *(uint4*)(smem + AT_QL + so) = *(const uint4*)(Ql_g + goff);
        }
    }

    float l_acc[2] = {0.f, 0.f};
    int ps = 0, pp = 0;
    bool pv_pending = false;

    const uint64_t AOFF[8] = {0,2,4,6,1024,1026,1028,1030};
    const uint64_t BOFF[8] = {0,2,4,6,512,514,516,518};
    uint64_t qdh = make_desc_sw128(sb + AT_QH);
    uint64_t qdl = make_desc_sw128(sb + AT_QL);

    for (int pass = 0; pass < 2; pass++) {
        const bf16* Kph = pass ? YKh_g : Kh_g;
        const bf16* Kpl = pass ? YKl_g : Kl_g;
        const fp16* Vph = pass ? YVTh_g : VTh_g;
        const fp16* Vpl = pass ? YVTl_g : VTl_g;
        int Sk = pass ? LY_ : S_;
        int ntile = Sk / 64;
        uint32_t ocol = pass ? 192u : 64u;
        size_t vbase = ((size_t)(b * H_ + h)) * HD_ * Sk;

        if (pv_pending) { mbar_wait_parity(sb + 16, pp); pp ^= 1; pv_pending = false; }

        {
            uint32_t stg = AT_STG0;
#pragma unroll
            for (int r = 0; r < 4; r++) {
                int e = tid + r * 256;
                int key = e >> 4;
                int ch = e & 15;
                size_t goff = (size_t)(b * Sk + key) * HHD + h * HD_ + ch * 8;
                uint32_t byte = (uint32_t)((key >> 3) * 1024 + (ch >> 3) * 8192
                                           + (key & 7) * 128 + (ch & 7) * 16);
                uint32_t so = sw128(byte);
                *(uint4*)(smem + stg + SO_KH + so) = *(const uint4*)(Kph + goff);
                *(uint4*)(smem + stg + SO_KL + so) = *(const uint4*)(Kpl + goff);
            }
#pragma unroll
            for (int r = 0; r < 4; r++) {
                int e = tid + r * 256;
                int hd = e >> 3;
                int kc = e & 7;
                size_t goff = vbase + (size_t)hd * Sk + kc * 8;
                uint32_t so = sw128((uint32_t)(hd * 128 + kc * 16));
                *(uint4*)(smem + stg + SO_VH + so) = *(const uint4*)(Vph + goff);
                *(uint4*)(smem + stg + SO_VL + so) = *(const uint4*)(Vpl + goff);
            }
        }
        __syncthreads();
        if (wid == 0) {
            FENCE_ASYNC_SHARED();
            if (elect_one()) {
                uint64_t kh = make_desc_sw128(sb + AT_STG0 + SO_KH);
                uint64_t kl = make_desc_sw128(sb + AT_STG0 + SO_KL);
#pragma unroll
                for (int j = 0; j < 8; j++)
                    mma_f16_ss(tmem, qdh + AOFF[j], kh + BOFF[j], IDESC_S, j > 0);
#pragma unroll
                for (int j = 0; j < 8; j++)
                    mma_f16_ss(tmem, qdl + AOFF[j], kh + BOFF[j], IDESC_S, 1u);
#pragma unroll
                for (int j = 0; j < 8; j++)
                    mma_f16_ss(tmem, qdh + AOFF[j], kl + BOFF[j], IDESC_S, 1u);
                TCGEN05_COMMIT(sb + 8);
            }
        }

        for (int t = 0; t < ntile; t++) {
            if (t >= 1) { mbar_wait_parity(sb + 16, pp); pp ^= 1; }

            if (t + 1 < ntile) {
                uint32_t stg = AT_STG0 + (uint32_t)((t + 1) & 1) * AT_SSTRIDE;
                int key0 = (t + 1) * 64;
#pragma unroll
                for (int r = 0; r < 4; r++) {
                    int e = tid + r * 256;
                    int key = e >> 4;
                    int ch = e & 15;
                    size_t goff = (size_t)(b * Sk + key0 + key) * HHD + h * HD_ + ch * 8;
                    uint32_t byte = (uint32_t)((key >> 3) * 1024 + (ch >> 3) * 8192
                                               + (key & 7) * 128 + (ch & 7) * 16);
                    uint32_t so = sw128(byte);
                    *(uint4*)(smem + stg + SO_KH + so) = *(const uint4*)(Kph + goff);
                    *(uint4*)(smem + stg + SO_KL + so) = *(const uint4*)(Kpl + goff);
                }
#pragma unroll
                for (int r = 0; r < 4; r++) {
                    int e = tid + r * 256;
                    int hd = e >> 3;
                    int kc = e & 7;
                    size_t goff = vbase + (size_t)hd * Sk + key0 + kc * 8;
                    uint32_t so = sw128((uint32_t)(hd * 128 + kc * 16));
                    *(uint4*)(smem + stg + SO_VH + so) = *(const uint4*)(Vph + goff);
                    *(uint4*)(smem + stg + SO_VL + so) = *(const uint4*)(Vpl + goff);
                }
            }

            mbar_wait_parity(sb + 8, ps); ps ^= 1;
            TCGEN05_FENCE_AFTER();

            if (wid < 4) {
                uint32_t pbase = (uint32_t)(row * 128);
#pragma unroll
                for (int c = 0; c < 2; c++) {
                    uint32_t sr[32];
                    TCGEN05_LD_X32(sr, tmem + (uint32_t)c * 32);
                    TCGEN05_WAIT_LD();
                    float lsum = 0.f;
#pragma unroll
                    for (int j = 0; j < 16; j++) {
                        float p0 = __expf(__uint_as_float(sr[2 * j])     - EXP_SHIFT);
                        float p1 = __expf(__uint_as_float(sr[2 * j + 1]) - EXP_SHIFT);
                        lsum += p0 + p1;
                        __half2 ph2 = __floats2half2_rn(p0, p1);
                        uint32_t so = sw128(pbase + c * 64 + j * 4);
                        *(uint32_t*)(smem + AT_P + so) = *(uint32_t*)&ph2;
                    }
                    l_acc[pass] += lsum;
                }
                TCGEN05_FENCE_BEFORE();
            }
            __syncthreads();

            if (wid == 0) {
                FENCE_ASYNC_SHARED();
                TCGEN05_FENCE_AFTER();
                if (elect_one()) {
                    uint32_t stg = AT_STG0 + (uint32_t)(t & 1) * AT_SSTRIDE;
                    uint64_t pd = make_desc_sw128(sb + AT_P);
                    uint64_t vh = make_desc_sw128(sb + stg + SO_VH);
                    uint64_t vl = make_desc_sw128(sb + stg + SO_VL);
#pragma unroll
                    for (int j = 0; j < 4; j++)
                        mma_f16_ss(tmem + ocol, pd + j * 2, vh + j * 2, IDESC_PV16,
                                   (t > 0 || j > 0) ? 1u : 0u);
#pragma unroll
                    for (int j = 0; j < 4; j++)
                        mma_f16_ss(tmem + ocol, pd + j * 2, vl + j * 2, IDESC_PV16, 1u);
                    TCGEN05_COMMIT(sb + 16);

                    if (t + 1 < ntile) {
                        uint32_t stg2 = AT_STG0 + (uint32_t)((t + 1) & 1) * AT_SSTRIDE;
                        uint64_t kh = make_desc_sw128(sb + stg2 + SO_KH);
                        uint64_t kl = make_desc_sw128(sb + stg2 + SO_KL);
#pragma unroll
                        for (int j = 0; j < 8; j++)
                            mma_f16_ss(tmem, qdh + AOFF[j], kh + BOFF[j], IDESC_S, j > 0);
#pragma unroll
                        for (int j = 0; j < 8; j++)
                            mma_f16_ss(tmem, qdl + AOFF[j], kh + BOFF[j], IDESC_S, 1u);
#pragma unroll
                        for (int j = 0; j < 8; j++)
                            mma_f16_ss(tmem, qdh + AOFF[j], kl + BOFF[j], IDESC_S, 1u);
                        TCGEN05_COMMIT(sb + 8);
                    }
                }
            }
            pv_pending = true;
            __syncthreads();
        }
    }

    if (pv_pending) { mbar_wait_parity(sb + 16, pp); pp ^= 1; }
    TCGEN05_FENCE_AFTER();

    if (wid < 4) {
        float inv0 = 1.f / l_acc[0];
        float inv1 = 1.f / l_acc[1];
        float gt = tanhf(gate[h]);
        size_t obase = (size_t)(b * S_ + s0 + row) * HHD + h * HD_;
#pragma unroll
        for (int c0 = 0; c0 < 128; c0 += 32) {
            uint32_t osr[32], ocr[32];
            TCGEN05_LD_X32(osr, tmem + 64  + c0);
            TCGEN05_WAIT_LD();
            TCGEN05_LD_X32(ocr, tmem + 192 + c0);
            TCGEN05_WAIT_LD();
#pragma unroll
            for (int j = 0; j < 32; j += 2) {
                float o0 = __uint_as_float(osr[j])     * inv0 + gt * __uint_as_float(ocr[j])     * inv1;
                float o1 = __uint_as_float(osr[j + 1]) * inv0 + gt * __uint_as_float(ocr[j + 1]) * inv1;
                bf16 h0, l0, h1, l1;
                split_hl(o0, h0, l0);
                split_hl(o1, h1, l1);
                *(uint32_t*)(Oh + obase + c0 + j) = pack2(__bfloat162float(h0), __bfloat162float(h1));
                *(uint32_t*)(Ol + obase + c0 + j) = pack2(__bfloat162float(l0), __bfloat162float(l1));
            }
        }
        TCGEN05_FENCE_BEFORE();
    }
    __syncthreads();
    if (tid == 0) { MBARRIER_INVAL(sb + 8); MBARRIER_INVAL(sb + 16); }
    if (wid == 0) TCGEN05_DEALLOC(tmem, 512);
#endif
}

// =====================================================================
// elementwise fp32 -> bf16 hi/lo split
// =====================================================================
__global__ void split_kernel(const float* __restrict__ in,
                             bf16* __restrict__ hi, bf16* __restrict__ lo,
                             int n)
{
    int i = (blockIdx.x * blockDim.x + threadIdx.x) * 4;
    if (i >= n) return;
    float4 v = *(const float4*)(in + i);
    bf16 h0, l0, h1, l1, h2, l2, h3, l3;
    split_hl(v.x, h0, l0); split_hl(v.y, h1, l1);
    split_hl(v.z, h2, l2); split_hl(v.w, h3, l3);
    uint2 hp, lp;
    ((bf16*)&hp)[0] = h0; ((bf16*)&hp)[1] = h1; ((bf16*)&hp)[2] = h2; ((bf16*)&hp)[3] = h3;
    ((bf16*)&lp)[0] = l0; ((bf16*)&lp)[1] = l1; ((bf16*)&lp)[2] = l2; ((bf16*)&lp)[3] = l3;
    *(uint2*)(hi + i) = hp;
    *(uint2*)(lo + i) = lp;
}

// =====================================================================
// V transpose + fp16 hi/lo split (vectorized writes)
// =====================================================================
__global__ void vtrans_split_kernel(const float* __restrict__ in,
                                    fp16* __restrict__ oh, fp16* __restrict__ ol,
                                    int Sk)
{
    __shared__ float t[32][33];
    int s0 = blockIdx.x * 32, d0 = blockIdx.y * 32;
    int bh = blockIdx.z;
    int b = bh / H_, h = bh % H_;
    int tx = threadIdx.x, ty = threadIdx.y;
#pragma unroll
    for (int i = ty; i < 32; i += 8)
        t[i][tx] = in[((size_t)(b * Sk + s0 + i)) * HHD + h * HD_ + d0 + tx];
    __syncthreads();
    int orow = ty * 4 + (tx >> 3);
    int oc = (tx & 7) * 4;
    uint2 hp, lp;
#pragma unroll
    for (int kk = 0; kk < 4; kk++) {
        fp16 hh, ll;
        split_hl16(t[oc + kk][orow], hh, ll);
        ((fp16*)&hp)[kk] = hh;
        ((fp16*)&lp)[kk] = ll;
    }
    size_t o = ((size_t)bh * HD_ + d0 + orow) * Sk + s0 + oc;
    *(uint2*)(oh + o) = hp;
    *(uint2*)(ol + o) = lp;
}

// =====================================================================
// 2048x2048 transpose + bf16 hi/lo split (vectorized writes)
// =====================================================================
__global__ void transpose_split_kernel(const float* __restrict__ in,
                                       bf16* __restrict__ oh,
                                       bf16* __restrict__ ol)
{
    __shared__ float t[32][33];
    int c0 = blockIdx.x * 32, r0 = blockIdx.y * 32;
    int tx = threadIdx.x, ty = threadIdx.y;
#pragma unroll
    for (int i = ty; i < 32; i += 8)
        t[i][tx] = in[(size_t)(r0 + i) * 2048 + c0 + tx];
    __syncthreads();
    int orow = ty * 4 + (tx >> 3);
    int oc = (tx & 7) * 4;
    uint2 hp, lp;
#pragma unroll
    for (int kk = 0; kk < 4; kk++) {
        bf16 hh, ll;
        split_hl(t[oc + kk][orow], hh, ll);
        ((bf16*)&hp)[kk] = hh;
        ((bf16*)&lp)[kk] = ll;
    }
    size_t o = (size_t)(c0 + orow) * 2048 + r0 + oc;
    *(uint2*)(oh + o) = hp;
    *(uint2*)(ol + o) = lp;
}

// =====================================================================
// Fused LayerNorm (+optional RoPE, +scale) -> bf16 hi/lo outputs
// =====================================================================
__global__ void ln_rope_split_kernel(const float* __restrict__ in,
                                     const float* __restrict__ w,
                                     const float* __restrict__ bias,
                                     const float* __restrict__ freqs,
                                     int Smod, float eps, float oscale, int do_rope,
                                     bf16* __restrict__ oh, bf16* __restrict__ ol)
{
    __shared__ float red[32];
    int row = blockIdx.x;
    int tid = threadIdx.x;
    const float* p = in + (size_t)row * HHD;
    int base = tid * 8;

    float4 a = *(const float4*)(p + base);
    float4 c = *(const float4*)(p + base + 4);
    float v[8] = {a.x, a.y, a.z, a.w, c.x, c.y, c.z, c.w};

    float s1 = 0.f, s2 = 0.f;
#pragma unroll
    for (int j = 0; j < 8; j++) { s1 += v[j]; s2 += v[j] * v[j]; }
#pragma unroll
    for (int o = 16; o > 0; o >>= 1) {
        s1 += __shfl_down_sync(0xffffffffu, s1, o);
        s2 += __shfl_down_sync(0xffffffffu, s2, o);
    }
    int wid = tid >> 5, lane = tid & 31;
    if (lane == 0) { red[wid] = s1; red[8 + wid] = s2; }
    __syncthreads();
    if (tid == 0) {
        float t1 = 0.f, t2 = 0.f;
#pragma unroll
        for (int i = 0; i < 8; i++) { t1 += red[i]; t2 += red[8 + i]; }
        red[16] = t1; red[17] = t2;
    }
    __syncthreads();
    float mean = red[16] * (1.f / HHD);
    float var  = red[17] * (1.f / HHD) - mean * mean;
    float rstd = rsqrtf(fmaxf(var, 0.f) + eps);

#pragma unroll
    for (int j = 0; j < 8; j++) {
        int g = base + j;
        v[j] = (v[j] - mean) * rstd * w[g] + bias[g];
    }

    if (do_rope) {
        int s = row % Smod;
        const float* fr = freqs + (size_t)s * (HD_ / 2) * 2;
#pragma unroll
        for (int jp = 0; jp < 4; jp++) {
            int g = base + 2 * jp;
            int pidx = (g & (HD_ - 1)) >> 1;
            float cs = fr[pidx * 2 + 0];
            float sn = fr[pidx * 2 + 1];
            float x0 = v[2 * jp], x1 = v[2 * jp + 1];
            v[2 * jp]     = x0 * cs - x1 * sn;
            v[2 * jp + 1] = x0 * sn + x1 * cs;
        }
    }

    uint2 hp, lp;
#pragma unroll
    for (int j = 0; j < 8; j++) {
        float x = v[j] * oscale;
        bf16 hh, ll;
        split_hl(x, hh, ll);
        ((bf16*)&hp)[j & 3] = hh;
        ((bf16*)&lp)[j & 3] = ll;
        if ((j & 3) == 3) {
            *(uint2*)(oh + (size_t)row * HHD + base + j - 3) = hp;
            *(uint2*)(ol + (size_t)row * HHD + base + j - 3) = lp;
        }
    }
}

// =====================================================================
// launch — fork/join streams: y-chain + wo transpose run concurrently
// with the x-chain; all join before fattn.
// =====================================================================
static cudaStream_t g_s1 = nullptr, g_s2 = nullptr;
static cudaEvent_t  g_evRoot = nullptr, g_ev1 = nullptr, g_ev2 = nullptr;

extern "C" void kernel_launch(void* const* d_in, const int* in_sizes, int n_in,
                              void* d_out, int out_size)
{
    const float* x     = (const float*)d_in[0];
    const float* freqs = (const float*)d_in[2];
    const float* y     = (const float*)d_in[3];
    const float* wq    = (const float*)d_in[5];
    const float* wk    = (const float*)d_in[6];
    const float* wv    = (const float*)d_in[7];
    const float* wo    = (const float*)d_in[8];
    const float* wky   = (const float*)d_in[9];
    const float* wvy   = (const float*)d_in[10];
    const float* gate  = (const float*)d_in[11];
    const float* qn_w  = (const float*)d_in[12];
    const float* qn_b  = (const float*)d_in[13];
    const float* kn_w  = (const float*)d_in[14];
    const float* kn_b  = (const float*)d_in[15];
    const float* kyn_w = (const float*)d_in[16];
    const float* kyn_b = (const float*)d_in[17];
    float* out = (float*)d_out;

    float *q, *k, *v, *yk, *yv;
    bf16 *xh, *xl, *yh, *yl, *ath, *atl, *qh, *ql, *kh, *kl, *ykh, *ykl;
    fp16 *vth, *vtl, *yvth, *yvtl;
    bf16 *wqh, *wql, *wkh, *wkl, *wvh, *wvl, *woh, *wol, *wkyh, *wkyl, *wvyh, *wvyl;
    cudaGetSymbolAddress((void**)&q,    g_q);
    cudaGetSymbolAddress((void**)&k,    g_k);
    cudaGetSymbolAddress((void**)&v,    g_v);
    cudaGetSymbolAddress((void**)&yk,   g_yk);
    cudaGetSymbolAddress((void**)&yv,   g_yv);
    cudaGetSymbolAddress((void**)&xh,   g_xh);
    cudaGetSymbolAddress((void**)&xl,   g_xl);
    cudaGetSymbolAddress((void**)&yh,   g_yh);
    cudaGetSymbolAddress((void**)&yl,   g_yl);
    cudaGetSymbolAddress((void**)&ath,  g_ath);
    cudaGetSymbolAddress((void**)&atl,  g_atl);
    cudaGetSymbolAddress((void**)&qh,   g_qh);
    cudaGetSymbolAddress((void**)&ql,   g_ql);
    cudaGetSymbolAddress((void**)&kh,   g_kh);
    cudaGetSymbolAddress((void**)&kl,   g_kl);
    cudaGetSymbolAddress((void**)&ykh,  g_ykh);
    cudaGetSymbolAddress((void**)&ykl,  g_ykl);
    cudaGetSymbolAddress((void**)&vth,  g_vth);
    cudaGetSymbolAddress((void**)&vtl,  g_vtl);
    cudaGetSymbolAddress((void**)&yvth, g_yvth);
    cudaGetSymbolAddress((void**)&yvtl, g_yvtl);
    cudaGetSymbolAddress((void**)&wqh,  g_wqh);  cudaGetSymbolAddress((void**)&wql,  g_wql);
    cudaGetSymbolAddress((void**)&wkh,  g_wkh);  cudaGetSymbolAddress((void**)&wkl,  g_wkl);
    cudaGetSymbolAddress((void**)&wvh,  g_wvh);  cudaGetSymbolAddress((void**)&wvl,  g_wvl);
    cudaGetSymbolAddress((void**)&woh,  g_woh);  cudaGetSymbolAddress((void**)&wol,  g_wol);
    cudaGetSymbolAddress((void**)&wkyh, g_wkyh); cudaGetSymbolAddress((void**)&wkyl, g_wkyl);
    cudaGetSymbolAddress((void**)&wvyh, g_wvyh); cudaGetSymbolAddress((void**)&wvyl, g_wvyl);

    const int Mx = B_ * S_;    // 4096
    const int My = B_ * LY_;   // 1024

    if (!g_s1) {
        cudaStreamCreateWithFlags(&g_s1, cudaStreamNonBlocking);
        cudaStreamCreateWithFlags(&g_s2, cudaStreamNonBlocking);
        cudaEventCreateWithFlags(&g_evRoot, cudaEventDisableTiming);
        cudaEventCreateWithFlags(&g_ev1,    cudaEventDisableTiming);
        cudaEventCreateWithFlags(&g_ev2,    cudaEventDisableTiming);
    }

    cudaFuncSetAttribute(bf16x3_gemm_kernel,
                         cudaFuncAttributeMaxDynamicSharedMemorySize, GSMEM);
    cudaFuncSetAttribute(fattn_kernel,
                         cudaFuncAttributeMaxDynamicSharedMemorySize, AT_SMEM);

    dim3 tg(64, 64), tb(32, 8);
    dim3 gx(HHD / GBN, Mx / GBM);
    dim3 gy(HHD / GBN, My / GBM);
    const float scale = 0.08838834764831845f;

    // ---- fork ----
    cudaEventRecord(g_evRoot, 0);
    cudaStreamWaitEvent(g_s1, g_evRoot, 0);
    cudaStreamWaitEvent(g_s2, g_evRoot, 0);

    // ---- stream s1: y-chain (independent of x-chain until fattn) ----
    transpose_split_kernel<<<tg, tb, 0, g_s1>>>(wky, wkyh, wkyl);
    transpose_split_kernel<<<tg, tb, 0, g_s1>>>(wvy, wvyh, wvyl);
    split_kernel<<<(My * DY_ / 4 + 255) / 256, 256, 0, g_s1>>>(y, yh, yl, My * DY_);
    bf16x3_gemm_kernel<<<gy, 256, GSMEM, g_s1>>>(yh, yl, wkyh, wkyl, yk, My, HHD, DY_);
    bf16x3_gemm_kernel<<<gy, 256, GSMEM, g_s1>>>(yh, yl, wvyh, wvyl, yv, My, HHD, DY_);
    ln_rope_split_kernel<<<My, 256, 0, g_s1>>>(yk, kyn_w, kyn_b, freqs, 1, 1e-6f, 1.f, 0, ykh, ykl);
    vtrans_split_kernel<<<dim3(LY_ / 32, HD_ / 32, B_ * H_), dim3(32, 8), 0, g_s1>>>(yv, yvth, yvtl, LY_);
    cudaEventRecord(g_ev1, g_s1);

    // ---- stream s2: wo transpose (needed only by out-projection) ----
    transpose_split_kernel<<<tg, tb, 0, g_s2>>>(wo, woh, wol);
    cudaEventRecord(g_ev2, g_s2);

    // ---- main stream: x-chain ----
    transpose_split_kernel<<<tg, tb>>>(wq, wqh, wql);
    transpose_split_kernel<<<tg, tb>>>(wk, wkh, wkl);
    transpose_split_kernel<<<tg, tb>>>(wv, wvh, wvl);
    split_kernel<<<(Mx * D_ / 4 + 255) / 256, 256>>>(x, xh, xl, Mx * D_);
    bf16x3_gemm_kernel<<<gx, 256, GSMEM>>>(xh, xl, wqh, wql, q, Mx, HHD, D_);
    bf16x3_gemm_kernel<<<gx, 256, GSMEM>>>(xh, xl, wkh, wkl, k, Mx, HHD, D_);
    bf16x3_gemm_kernel<<<gx, 256, GSMEM>>>(xh, xl, wvh, wvl, v, Mx, HHD, D_);
    ln_rope_split_kernel<<<Mx, 256>>>(q, qn_w, qn_b, freqs, S_, 1e-5f, scale, 1, qh, ql);
    ln_rope_split_kernel<<<Mx, 256>>>(k, kn_w, kn_b, freqs, S_, 1e-5f, 1.f, 1, kh, kl);
    vtrans_split_kernel<<<dim3(S_ / 32, HD_ / 32, B_ * H_), dim3(32, 8)>>>(v, vth, vtl, S_);

    // ---- join: fattn needs y-chain outputs; out-proj needs wo ----
    cudaStreamWaitEvent(0, g_ev1, 0);
    cudaStreamWaitEvent(0, g_ev2, 0);

    fattn_kernel<<<dim3(S_ / 128, H_, B_), 256, AT_SMEM>>>(
        qh, ql, kh, kl, vth, vtl, ykh, ykl, yvth, yvtl, gate, ath, atl);

    bf16x3_gemm_kernel<<<dim3(D_ / GBN, Mx / GBM), 256, GSMEM>>>(
        ath, atl, woh, wol, out, Mx, D_, HHD);
}

// round 13
// speedup vs baseline: 1.3281x; 1.3281x over previous
#include <cuda_runtime.h>
#include <cuda_bf16.h>
#include <cuda_fp16.h>
#include <math.h>
#include <stdint.h>

#define B_   2
#define S_   2048
#define D_   2048
#define H_   16
#define HD_  128
#define LY_  512
#define DY_  2048
#define HHD  2048   // H*HD

typedef __nv_bfloat16 bf16;
typedef __half fp16;

// ---------------- scratch (no allocations allowed) ----------------
__device__ float g_q  [B_*S_*HHD];
__device__ float g_k  [B_*S_*HHD];
__device__ float g_v  [B_*S_*HHD];
__device__ float g_yk [B_*LY_*HHD];
__device__ float g_yv [B_*LY_*HHD];
// bf16 hi/lo splits
__device__ bf16 g_xh [B_*S_*D_],   g_xl [B_*S_*D_];
__device__ bf16 g_yh [B_*LY_*DY_], g_yl [B_*LY_*DY_];
__device__ bf16 g_ath[B_*S_*HHD],  g_atl[B_*S_*HHD];
__device__ bf16 g_qh [B_*S_*HHD],  g_ql [B_*S_*HHD];
__device__ bf16 g_kh [B_*S_*HHD],  g_kl [B_*S_*HHD];
__device__ bf16 g_ykh[B_*LY_*HHD], g_ykl[B_*LY_*HHD];
// fp16 hi/lo transposed V: [b][h][hd][s]
__device__ fp16 g_vth [B_*H_*HD_*S_],  g_vtl [B_*H_*HD_*S_];
__device__ fp16 g_yvth[B_*H_*HD_*LY_], g_yvtl[B_*H_*HD_*LY_];
// transposed + hi/lo split weights [N][K] bf16
__device__ bf16 g_wqh [HHD*D_],  g_wql [HHD*D_];
__device__ bf16 g_wkh [HHD*D_],  g_wkl [HHD*D_];
__device__ bf16 g_wvh [HHD*D_],  g_wvl [HHD*D_];
__device__ bf16 g_woh [D_*HHD],  g_wol [D_*HHD];
__device__ bf16 g_wkyh[HHD*DY_], g_wkyl[HHD*DY_];
__device__ bf16 g_wvyh[HHD*DY_], g_wvyl[HHD*DY_];

// =====================================================================
// Generic helpers
// =====================================================================
__device__ __forceinline__ uint32_t smem_u32(const void* p) {
    uint32_t a;
    asm("{ .reg .u64 t; cvta.to.shared.u64 t, %1; cvt.u32.u64 %0, t; }"
        : "=r"(a) : "l"(p));
    return a;
}
#define MBARRIER_INIT(addr, cnt) \
    asm volatile("mbarrier.init.shared.b64 [%0], %1;" :: "r"(addr), "r"(cnt) : "memory")
#define MBARRIER_INVAL(addr) \
    asm volatile("mbarrier.inval.shared.b64 [%0];" :: "r"(addr) : "memory")

__device__ __forceinline__ void mbar_wait_parity(uint32_t mbar, uint32_t parity) {
    asm volatile(
        "{\n\t.reg .pred P1;\n\t"
        "WAIT_LOOP_%=:\n\t"
        "mbarrier.try_wait.parity.acquire.cta.shared::cta.b64 P1, [%0], %1, 0x989680;\n\t"
        "@P1 bra.uni WAIT_DONE_%=;\n\t"
        "bra.uni WAIT_LOOP_%=;\n\t"
        "WAIT_DONE_%=:\n\t}"
        :: "r"(mbar), "r"(parity) : "memory");
}

__device__ __forceinline__ uint32_t sw128(uint32_t off) {
    return off ^ ((off >> 3) & 0x70);
}

__device__ __forceinline__ void split_hl(float x, bf16& h, bf16& l) {
    h = __float2bfloat16_rn(x);
    l = __float2bfloat16_rn(x - __bfloat162float(h));
}
__device__ __forceinline__ void split_hl16(float x, fp16& h, fp16& l) {
    h = __float2half_rn(x);
    l = __float2half_rn(x - __half2float(h));
}

__device__ __forceinline__ uint32_t pack2(float lo, float hi) {
    __nv_bfloat162 t = __floats2bfloat162_rn(lo, hi);
    return *(uint32_t*)&t;
}

// =====================================================================
// tcgen05 helpers — arch-specific pass only
// =====================================================================
#if defined(__CUDA_ARCH_FEAT_SM103_ALL) || !defined(__CUDA_ARCH__)

__device__ __forceinline__ uint32_t elect_one() {
    uint32_t pred;
    asm volatile("{\n\t.reg .pred p;\n\telect.sync _|p, 0xFFFFFFFF;\n\t"
                 "selp.b32 %0, 1, 0, p;\n\t}" : "=r"(pred));
    return pred;
}
#define TCGEN05_ALLOC(smem_addr, ncols) \
    asm volatile("tcgen05.alloc.cta_group::1.sync.aligned.shared::cta.b32 [%0], %1;" \
                 :: "r"(smem_addr), "r"(ncols) : "memory")
#define TCGEN05_DEALLOC(tmem, ncols) \
    asm volatile("tcgen05.dealloc.cta_group::1.sync.aligned.b32 %0, %1;" :: "r"(tmem), "r"(ncols))
#define TCGEN05_RELINQ() \
    asm volatile("tcgen05.relinquish_alloc_permit.cta_group::1.sync.aligned;")
#define TCGEN05_COMMIT(mbar) \
    asm volatile("tcgen05.commit.cta_group::1.mbarrier::arrive::one.shared::cluster.b64 [%0];" \
                 :: "r"(mbar) : "memory")
#define TCGEN05_WAIT_LD() asm volatile("tcgen05.wait::ld.sync.aligned;" ::: "memory")
#define TCGEN05_FENCE_BEFORE() asm volatile("tcgen05.fence::before_thread_sync;" ::: "memory")
#define TCGEN05_FENCE_AFTER()  asm volatile("tcgen05.fence::after_thread_sync;" ::: "memory")
#define FENCE_ASYNC_SHARED() asm volatile("fence.proxy.async.shared::cta;" ::: "memory")

#define TCGEN05_LD_X32(r, tmem_addr) \
    asm volatile( \
        "tcgen05.ld.sync.aligned.32x32b.x32.b32 " \
        "{%0, %1, %2, %3, %4, %5, %6, %7, " \
        " %8, %9, %10, %11, %12, %13, %14, %15, " \
        " %16, %17, %18, %19, %20, %21, %22, %23, " \
        " %24, %25, %26, %27, %28, %29, %30, %31}, [%32];" \
        : "=r"((r)[0]),  "=r"((r)[1]),  "=r"((r)[2]),  "=r"((r)[3]), \
          "=r"((r)[4]),  "=r"((r)[5]),  "=r"((r)[6]),  "=r"((r)[7]), \
          "=r"((r)[8]),  "=r"((r)[9]),  "=r"((r)[10]), "=r"((r)[11]), \
          "=r"((r)[12]), "=r"((r)[13]), "=r"((r)[14]), "=r"((r)[15]), \
          "=r"((r)[16]), "=r"((r)[17]), "=r"((r)[18]), "=r"((r)[19]), \
          "=r"((r)[20]), "=r"((r)[21]), "=r"((r)[22]), "=r"((r)[23]), \
          "=r"((r)[24]), "=r"((r)[25]), "=r"((r)[26]), "=r"((r)[27]), \
          "=r"((r)[28]), "=r"((r)[29]), "=r"((r)[30]), "=r"((r)[31]) \
        : "r"(tmem_addr))

// SW128 K-major smem descriptor: layout=SW128(2), version=1, SBO=64, LBO=1
__device__ __forceinline__ uint64_t make_desc_sw128(uint32_t addr) {
    uint64_t d = (uint64_t(2) << 61) | (uint64_t(1) << 46)
               | (uint64_t(64) << 32) | (uint64_t(1) << 16);
    return d | ((uint64_t)(addr >> 4) & 0x3FFF);
}

// f16-kind SS MMA (bf16 or fp16 per idesc)
__device__ __forceinline__ void mma_f16_ss(uint32_t d_tmem, uint64_t a_desc,
                                           uint64_t b_desc, uint32_t idesc,
                                           uint32_t enable) {
    asm volatile(
        "{\n\t.reg .pred p;\n\tsetp.ne.u32 p, %5, 0;\n\t"
        "tcgen05.mma.cta_group::1.kind::f16 [%0], %1, %2, %3, {%4, %4, %4, %4}, p;\n\t}"
        :: "r"(d_tmem), "l"(a_desc), "l"(b_desc), "r"(idesc), "r"(0u), "r"(enable)
        : "memory");
}
#endif

// =====================================================================
// bf16x3 GEMM (R8/R11 form): C = (Ah+Al) @ (Bh+Bl)^T
// =====================================================================
#define GBM 128
#define GBN 256
#define GBK 64
#define STG_STRIDE 98304
#define OFF_AH 0
#define OFF_AL 16384
#define OFF_BH 32768
#define OFF_BL 65536
#define GSMEM (1024 + 2*STG_STRIDE)

#define BF16_IDESC ((1u<<4) | (1u<<7) | (1u<<10) | ((GBN/8)<<17) | ((GBM/16)<<24))

__global__ void __launch_bounds__(256, 1) bf16x3_gemm_kernel(
    const bf16* __restrict__ Ah, const bf16* __restrict__ Al,
    const bf16* __restrict__ Bh, const bf16* __restrict__ Bl,
    float* __restrict__ C, int M, int N, int K)
{
#if defined(__CUDA_ARCH_FEAT_SM103_ALL) || !defined(__CUDA_ARCH__)
    extern __shared__ char smem[];
    uint32_t sb = smem_u32(smem);
    int tid = threadIdx.x, wid = tid >> 5, lane = tid & 31;
    int bm0 = blockIdx.y * GBM, bn0 = blockIdx.x * GBN;

    if (wid == 0) TCGEN05_ALLOC(sb + 0, 256);
    if (tid == 0) {
        MBARRIER_INIT(sb + 8, 1);
        MBARRIER_INIT(sb + 16, 1);
        MBARRIER_INIT(sb + 24, 1);
    }
    __syncthreads();
    uint32_t tmem;
    asm volatile("ld.shared.b32 %0, [%1];" : "=r"(tmem) : "r"(sb + 0));
    if (wid == 0) TCGEN05_RELINQ();

    int ph0 = 0, ph1 = 0;
    const int niter = K / GBK;

    for (int i = 0; i < niter; i++) {
        int s = i & 1;
        uint32_t stg = 1024 + s * STG_STRIDE;
        if (i >= 2) {
            if (s == 0) { mbar_wait_parity(sb + 8,  ph0); ph0 ^= 1; }
            else        { mbar_wait_parity(sb + 16, ph1); ph1 ^= 1; }
        }
        int k0 = i * GBK;
        {
#pragma unroll
            for (int r = 0; r < 4; r++) {
                int e = tid + r * 256;
                int row = e >> 3;
                int ch = e & 7;
                size_t goff = (size_t)(bm0 + row) * K + k0 + ch * 8;
                uint32_t soff = sw128((uint32_t)(row * 128 + ch * 16));
                *(uint4*)(smem + stg + OFF_AH + soff) = *(const uint4*)(Ah + goff);
                *(uint4*)(smem + stg + OFF_AL + soff) = *(const uint4*)(Al + goff);
            }
        }
        {
#pragma unroll
            for (int r = 0; r < 8; r++) {
                int e = tid + r * 256;
                int row = e >> 3;
                int ch = e & 7;
                size_t goff = (size_t)(bn0 + row) * K + k0 + ch * 8;
                uint32_t soff = sw128((uint32_t)(row * 128 + ch * 16));
                *(uint4*)(smem + stg + OFF_BH + soff) = *(const uint4*)(Bh + goff);
                *(uint4*)(smem + stg + OFF_BL + soff) = *(const uint4*)(Bl + goff);
            }
        }
        __syncthreads();

        if (wid == 0) {
            FENCE_ASYNC_SHARED();
            if (elect_one()) {
                uint64_t ah = make_desc_sw128(sb + stg + OFF_AH);
                uint64_t al = make_desc_sw128(sb + stg + OFF_AL);
                uint64_t bh = make_desc_sw128(sb + stg + OFF_BH);
                uint64_t bl = make_desc_sw128(sb + stg + OFF_BL);
#pragma unroll
                for (int j = 0; j < 4; j++)
                    mma_f16_ss(tmem, ah + j * 2, bh + j * 2, BF16_IDESC,
                               (i > 0 || j > 0) ? 1u : 0u);
#pragma unroll
                for (int j = 0; j < 4; j++)
                    mma_f16_ss(tmem, ah + j * 2, bl + j * 2, BF16_IDESC, 1u);
#pragma unroll
                for (int j = 0; j < 4; j++)
                    mma_f16_ss(tmem, al + j * 2, bh + j * 2, BF16_IDESC, 1u);
                TCGEN05_COMMIT(sb + 8 + 8 * s);
            }
        }
    }

    __syncthreads();
    if (wid == 0 && elect_one()) TCGEN05_COMMIT(sb + 24);
    mbar_wait_parity(sb + 24, 0);
    TCGEN05_FENCE_AFTER();

    if (wid < 4) {
        float* crow = C + (size_t)(bm0 + wid * 32 + lane) * N + bn0;
#pragma unroll
        for (int c0 = 0; c0 < GBN; c0 += 32) {
            uint32_t r[32];
            TCGEN05_LD_X32(r, tmem + c0);
            TCGEN05_WAIT_LD();
#pragma unroll
            for (int j = 0; j < 32; j += 4) {
                *(float4*)(crow + c0 + j) = make_float4(
                    __uint_as_float(r[j]), __uint_as_float(r[j + 1]),
                    __uint_as_float(r[j + 2]), __uint_as_float(r[j + 3]));
            }
        }
    }
    __syncthreads();
    if (tid == 0) {
        MBARRIER_INVAL(sb + 8); MBARRIER_INVAL(sb + 16); MBARRIER_INVAL(sb + 24);
    }
    if (wid == 0) TCGEN05_DEALLOC(tmem, 256);
#endif
}

// =====================================================================
// Flash attention v2.1: R11 base + 8-warp softmax (column-split).
// TMEM: S 0-63 | O_self 64-191 | O_cross 192-319
// =====================================================================
#define AT_QH 1024
#define AT_QL (AT_QH + 32768)
#define AT_STG0 (AT_QL + 32768)
#define AT_SSTRIDE 65536
#define SO_KH 0
#define SO_KL 16384
#define SO_VH 32768
#define SO_VL 49152
#define AT_P  (AT_STG0 + 2*AT_SSTRIDE)
#define AT_SMEM (AT_P + 16384)

#define IDESC_S    ((1u<<4) | (1u<<7) | (1u<<10) | ((64/8)<<17)  | ((128/16)<<24))
#define IDESC_PV16 ((1u<<4) | (0u<<7) | (0u<<10) | ((128/8)<<17) | ((128/16)<<24))
#define EXP_SHIFT 6.0f

__global__ void __launch_bounds__(256, 1) fattn_kernel(
    const bf16* __restrict__ Qh_g, const bf16* __restrict__ Ql_g,
    const bf16* __restrict__ Kh_g, const bf16* __restrict__ Kl_g,
    const fp16* __restrict__ VTh_g, const fp16* __restrict__ VTl_g,
    const bf16* __restrict__ YKh_g, const bf16* __restrict__ YKl_g,
    const fp16* __restrict__ YVTh_g, const fp16* __restrict__ YVTl_g,
    const float* __restrict__ gate,
    bf16* __restrict__ Oh, bf16* __restrict__ Ol)
{
#if defined(__CUDA_ARCH_FEAT_SM103_ALL) || !defined(__CUDA_ARCH__)
    extern __shared__ char smem[];
    uint32_t sb = smem_u32(smem);
    int tid = threadIdx.x, wid = tid >> 5, lane = tid & 31;
    int qt = blockIdx.x, h = blockIdx.y, b = blockIdx.z;
    int s0 = qt * 128;
    int half = wid >> 2;                  // S column half owned (softmax)
    int rowq = (wid & 3) * 32 + lane;     // q row / TMEM lane owned

    if (wid == 0) TCGEN05_ALLOC(sb + 0, 512);
    if (tid == 0) { MBARRIER_INIT(sb + 8, 1); MBARRIER_INIT(sb + 16, 1); }
    __syncthreads();
    uint32_t tmem;
    asm volatile("ld.shared.b32 %0, [%1];" : "=r"(tmem) : "r"(sb + 0));
    if (wid == 0) TCGEN05_RELINQ();

    // ---- load Q tile once ----
    {
#pragma unroll
        for (int r = 0; r < 8; r++) {
            int e = tid + r * 256;
            int qr = e >> 4;
            int ch = e & 15;
            size_t goff = (size_t)(b * S_ + s0 + qr) * HHD + h * HD_ + ch * 8;
            uint32_t byte = (uint32_t)((qr >> 3) * 1024 + (ch >> 3) * 16384
                                       + (qr & 7) * 128 + (ch & 7) * 16);
            uint32_t so = sw128(byte);
            *(uint4*)(smem + AT_QH + so) = *(const uint4*)(Qh_g + goff);
            *(uint4*)(smem + AT_QL + so) = *(const uint4*)(Ql_g + goff);
        }
    }

    float l_acc[2] = {0.f, 0.f};          // half-row sums per pass
    int ps = 0, pp = 0;
    bool pv_pending = false;

    const uint64_t AOFF[8] = {0,2,4,6,1024,1026,1028,1030};
    const uint64_t BOFF[8] = {0,2,4,6,512,514,516,518};
    uint64_t qdh = make_desc_sw128(sb + AT_QH);
    uint64_t qdl = make_desc_sw128(sb + AT_QL);

    for (int pass = 0; pass < 2; pass++) {
        const bf16* Kph = pass ? YKh_g : Kh_g;
        const bf16* Kpl = pass ? YKl_g : Kl_g;
        const fp16* Vph = pass ? YVTh_g : VTh_g;
        const fp16* Vpl = pass ? YVTl_g : VTl_g;
        int Sk = pass ? LY_ : S_;
        int ntile = Sk / 64;
        uint32_t ocol = pass ? 192u : 64u;
        size_t vbase = ((size_t)(b * H_ + h)) * HD_ * Sk;

        if (pv_pending) { mbar_wait_parity(sb + 16, pp); pp ^= 1; pv_pending = false; }

        {
            uint32_t stg = AT_STG0;
#pragma unroll
            for (int r = 0; r < 4; r++) {
                int e = tid + r * 256;
                int key = e >> 4;
                int ch = e & 15;
                size_t goff = (size_t)(b * Sk + key) * HHD + h * HD_ + ch * 8;
                uint32_t byte = (uint32_t)((key >> 3) * 1024 + (ch >> 3) * 8192
                                           + (key & 7) * 128 + (ch & 7) * 16);
                uint32_t so = sw128(byte);
                *(uint4*)(smem + stg + SO_KH + so) = *(const uint4*)(Kph + goff);
                *(uint4*)(smem + stg + SO_KL + so) = *(const uint4*)(Kpl + goff);
            }
#pragma unroll
            for (int r = 0; r < 4; r++) {
                int e = tid + r * 256;
                int hd = e >> 3;
                int kc = e & 7;
                size_t goff = vbase + (size_t)hd * Sk + kc * 8;
                uint32_t so = sw128((uint32_t)(hd * 128 + kc * 16));
                *(uint4*)(smem + stg + SO_VH + so) = *(const uint4*)(Vph + goff);
                *(uint4*)(smem + stg + SO_VL + so) = *(const uint4*)(Vpl + goff);
            }
        }
        __syncthreads();
        if (wid == 0) {
            FENCE_ASYNC_SHARED();
            if (elect_one()) {
                uint64_t kh = make_desc_sw128(sb + AT_STG0 + SO_KH);
                uint64_t kl = make_desc_sw128(sb + AT_STG0 + SO_KL);
#pragma unroll
                for (int j = 0; j < 8; j++)
                    mma_f16_ss(tmem, qdh + AOFF[j], kh + BOFF[j], IDESC_S, j > 0);
#pragma unroll
                for (int j = 0; j < 8; j++)
                    mma_f16_ss(tmem, qdl + AOFF[j], kh + BOFF[j], IDESC_S, 1u);
#pragma unroll
                for (int j = 0; j < 8; j++)
                    mma_f16_ss(tmem, qdh + AOFF[j], kl + BOFF[j], IDESC_S, 1u);
                TCGEN05_COMMIT(sb + 8);
            }
        }

        for (int t = 0; t < ntile; t++) {
            if (t >= 1) { mbar_wait_parity(sb + 16, pp); pp ^= 1; }

            if (t + 1 < ntile) {
                uint32_t stg = AT_STG0 + (uint32_t)((t + 1) & 1) * AT_SSTRIDE;
                int key0 = (t + 1) * 64;
#pragma unroll
                for (int r = 0; r < 4; r++) {
                    int e = tid + r * 256;
                    int key = e >> 4;
                    int ch = e & 15;
                    size_t goff = (size_t)(b * Sk + key0 + key) * HHD + h * HD_ + ch * 8;
                    uint32_t byte = (uint32_t)((key >> 3) * 1024 + (ch >> 3) * 8192
                                               + (key & 7) * 128 + (ch & 7) * 16);
                    uint32_t so = sw128(byte);
                    *(uint4*)(smem + stg + SO_KH + so) = *(const uint4*)(Kph + goff);
                    *(uint4*)(smem + stg + SO_KL + so) = *(const uint4*)(Kpl + goff);
                }
#pragma unroll
                for (int r = 0; r < 4; r++) {
                    int e = tid + r * 256;
                    int hd = e >> 3;
                    int kc = e & 7;
                    size_t goff = vbase + (size_t)hd * Sk + key0 + kc * 8;
                    uint32_t so = sw128((uint32_t)(hd * 128 + kc * 16));
                    *(uint4*)(smem + stg + SO_VH + so) = *(const uint4*)(Vph + goff);
                    *(uint4*)(smem + stg + SO_VL + so) = *(const uint4*)(Vpl + goff);
                }
            }

            mbar_wait_parity(sb + 8, ps); ps ^= 1;
            TCGEN05_FENCE_AFTER();

            // ---- softmax: ALL 8 warps, column-split (32 cols each) ----
            {
                uint32_t sr[32];
                TCGEN05_LD_X32(sr, tmem + (uint32_t)half * 32);
                TCGEN05_WAIT_LD();
                float lsum = 0.f;
                uint32_t pbase = (uint32_t)(rowq * 128 + half * 64);
#pragma unroll
                for (int j = 0; j < 16; j++) {
                    float p0 = __expf(__uint_as_float(sr[2 * j])     - EXP_SHIFT);
                    float p1 = __expf(__uint_as_float(sr[2 * j + 1]) - EXP_SHIFT);
                    lsum += p0 + p1;
                    __half2 ph2 = __floats2half2_rn(p0, p1);
                    uint32_t so = sw128(pbase + j * 4);
                    *(uint32_t*)(smem + AT_P + so) = *(uint32_t*)&ph2;
                }
                l_acc[pass] += lsum;
                TCGEN05_FENCE_BEFORE();
            }
            __syncthreads();

            if (wid == 0) {
                FENCE_ASYNC_SHARED();
                TCGEN05_FENCE_AFTER();
                if (elect_one()) {
                    uint32_t stg = AT_STG0 + (uint32_t)(t & 1) * AT_SSTRIDE;
                    uint64_t pd = make_desc_sw128(sb + AT_P);
                    uint64_t vh = make_desc_sw128(sb + stg + SO_VH);
                    uint64_t vl = make_desc_sw128(sb + stg + SO_VL);
#pragma unroll
                    for (int j = 0; j < 4; j++)
                        mma_f16_ss(tmem + ocol, pd + j * 2, vh + j * 2, IDESC_PV16,
                                   (t > 0 || j > 0) ? 1u : 0u);
#pragma unroll
                    for (int j = 0; j < 4; j++)
                        mma_f16_ss(tmem + ocol, pd + j * 2, vl + j * 2, IDESC_PV16, 1u);
                    TCGEN05_COMMIT(sb + 16);

                    if (t + 1 < ntile) {
                        uint32_t stg2 = AT_STG0 + (uint32_t)((t + 1) & 1) * AT_SSTRIDE;
                        uint64_t kh = make_desc_sw128(sb + stg2 + SO_KH);
                        uint64_t kl = make_desc_sw128(sb + stg2 + SO_KL);
#pragma unroll
                        for (int j = 0; j < 8; j++)
                            mma_f16_ss(tmem, qdh + AOFF[j], kh + BOFF[j], IDESC_S, j > 0);
#pragma unroll
                        for (int j = 0; j < 8; j++)
                            mma_f16_ss(tmem, qdl + AOFF[j], kh + BOFF[j], IDESC_S, 1u);
#pragma unroll
                        for (int j = 0; j < 8; j++)
                            mma_f16_ss(tmem, qdh + AOFF[j], kl + BOFF[j], IDESC_S, 1u);
                        TCGEN05_COMMIT(sb + 8);
                    }
                }
            }
            pv_pending = true;
            __syncthreads();
        }
    }

    if (pv_pending) { mbar_wait_parity(sb + 16, pp); pp ^= 1; }
    TCGEN05_FENCE_AFTER();

    // ---- combine half-row l sums via smem (P region free now) ----
    {
        float* sl = (float*)(smem + AT_P);
        sl[0 * 256 + half * 128 + rowq] = l_acc[0];
        sl[1 * 256 + half * 128 + rowq] = l_acc[1];
    }
    __syncthreads();

    // ---- epilogue: warps 0-3 combine self + gate*cross, write bf16 hi/lo ----
    if (wid < 4) {
        float* sl = (float*)(smem + AT_P);
        float inv0 = 1.f / (sl[0 * 256 + rowq] + sl[0 * 256 + 128 + rowq]);
        float inv1 = 1.f / (sl[1 * 256 + rowq] + sl[1 * 256 + 128 + rowq]);
        float gt = tanhf(gate[h]);
        size_t obase = (size_t)(b * S_ + s0 + rowq) * HHD + h * HD_;
#pragma unroll
        for (int c0 = 0; c0 < 128; c0 += 32) {
            uint32_t osr[32], ocr[32];
            TCGEN05_LD_X32(osr, tmem + 64  + c0);
            TCGEN05_WAIT_LD();
            TCGEN05_LD_X32(ocr, tmem + 192 + c0);
            TCGEN05_WAIT_LD();
#pragma unroll
            for (int j = 0; j < 32; j += 2) {
                float o0 = __uint_as_float(osr[j])     * inv0 + gt * __uint_as_float(ocr[j])     * inv1;
                float o1 = __uint_as_float(osr[j + 1]) * inv0 + gt * __uint_as_float(ocr[j + 1]) * inv1;
                bf16 h0, l0, h1, l1;
                split_hl(o0, h0, l0);
                split_hl(o1, h1, l1);
                *(uint32_t*)(Oh + obase + c0 + j) = pack2(__bfloat162float(h0), __bfloat162float(h1));
                *(uint32_t*)(Ol + obase + c0 + j) = pack2(__bfloat162float(l0), __bfloat162float(l1));
            }
        }
        TCGEN05_FENCE_BEFORE();
    }
    __syncthreads();
    if (tid == 0) { MBARRIER_INVAL(sb + 8); MBARRIER_INVAL(sb + 16); }
    if (wid == 0) TCGEN05_DEALLOC(tmem, 512);
#endif
}

// =====================================================================
// elementwise fp32 -> bf16 hi/lo split
// =====================================================================
__global__ void split_kernel(const float* __restrict__ in,
                             bf16* __restrict__ hi, bf16* __restrict__ lo,
                             int n)
{
    int i = (blockIdx.x * blockDim.x + threadIdx.x) * 4;
    if (i >= n) return;
    float4 v = *(const float4*)(in + i);
    bf16 h0, l0, h1, l1, h2, l2, h3, l3;
    split_hl(v.x, h0, l0); split_hl(v.y, h1, l1);
    split_hl(v.z, h2, l2); split_hl(v.w, h3, l3);
    uint2 hp, lp;
    ((bf16*)&hp)[0] = h0; ((bf16*)&hp)[1] = h1; ((bf16*)&hp)[2] = h2; ((bf16*)&hp)[3] = h3;
    ((bf16*)&lp)[0] = l0; ((bf16*)&lp)[1] = l1; ((bf16*)&lp)[2] = l2; ((bf16*)&lp)[3] = l3;
    *(uint2*)(hi + i) = hp;
    *(uint2*)(lo + i) = lp;
}

// =====================================================================
// V transpose + fp16 hi/lo split (vectorized writes)
// =====================================================================
__global__ void vtrans_split_kernel(const float* __restrict__ in,
                                    fp16* __restrict__ oh, fp16* __restrict__ ol,
                                    int Sk)
{
    __shared__ float t[32][33];
    int s0 = blockIdx.x * 32, d0 = blockIdx.y * 32;
    int bh = blockIdx.z;
    int b = bh / H_, h = bh % H_;
    int tx = threadIdx.x, ty = threadIdx.y;
#pragma unroll
    for (int i = ty; i < 32; i += 8)
        t[i][tx] = in[((size_t)(b * Sk + s0 + i)) * HHD + h * HD_ + d0 + tx];
    __syncthreads();
    int orow = ty * 4 + (tx >> 3);
    int oc = (tx & 7) * 4;
    uint2 hp, lp;
#pragma unroll
    for (int kk = 0; kk < 4; kk++) {
        fp16 hh, ll;
        split_hl16(t[oc + kk][orow], hh, ll);
        ((fp16*)&hp)[kk] = hh;
        ((fp16*)&lp)[kk] = ll;
    }
    size_t o = ((size_t)bh * HD_ + d0 + orow) * Sk + s0 + oc;
    *(uint2*)(oh + o) = hp;
    *(uint2*)(ol + o) = lp;
}

// =====================================================================
// 2048x2048 transpose + bf16 hi/lo split (vectorized writes)
// =====================================================================
__global__ void transpose_split_kernel(const float* __restrict__ in,
                                       bf16* __restrict__ oh,
                                       bf16* __restrict__ ol)
{
    __shared__ float t[32][33];
    int c0 = blockIdx.x * 32, r0 = blockIdx.y * 32;
    int tx = threadIdx.x, ty = threadIdx.y;
#pragma unroll
    for (int i = ty; i < 32; i += 8)
        t[i][tx] = in[(size_t)(r0 + i) * 2048 + c0 + tx];
    __syncthreads();
    int orow = ty * 4 + (tx >> 3);
    int oc = (tx & 7) * 4;
    uint2 hp, lp;
#pragma unroll
    for (int kk = 0; kk < 4; kk++) {
        bf16 hh, ll;
        split_hl(t[oc + kk][orow], hh, ll);
        ((bf16*)&hp)[kk] = hh;
        ((bf16*)&lp)[kk] = ll;
    }
    size_t o = (size_t)(c0 + orow) * 2048 + r0 + oc;
    *(uint2*)(oh + o) = hp;
    *(uint2*)(ol + o) = lp;
}

// =====================================================================
// Fused LayerNorm (+optional RoPE, +scale) -> bf16 hi/lo outputs
// =====================================================================
__global__ void ln_rope_split_kernel(const float* __restrict__ in,
                                     const float* __restrict__ w,
                                     const float* __restrict__ bias,
                                     const float* __restrict__ freqs,
                                     int Smod, float eps, float oscale, int do_rope,
                                     bf16* __restrict__ oh, bf16* __restrict__ ol)
{
    __shared__ float red[32];
    int row = blockIdx.x;
    int tid = threadIdx.x;
    const float* p = in + (size_t)row * HHD;
    int base = tid * 8;

    float4 a = *(const float4*)(p + base);
    float4 c = *(const float4*)(p + base + 4);
    float v[8] = {a.x, a.y, a.z, a.w, c.x, c.y, c.z, c.w};

    float s1 = 0.f, s2 = 0.f;
#pragma unroll
    for (int j = 0; j < 8; j++) { s1 += v[j]; s2 += v[j] * v[j]; }
#pragma unroll
    for (int o = 16; o > 0; o >>= 1) {
        s1 += __shfl_down_sync(0xffffffffu, s1, o);
        s2 += __shfl_down_sync(0xffffffffu, s2, o);
    }
    int wid = tid >> 5, lane = tid & 31;
    if (lane == 0) { red[wid] = s1; red[8 + wid] = s2; }
    __syncthreads();
    if (tid == 0) {
        float t1 = 0.f, t2 = 0.f;
#pragma unroll
        for (int i = 0; i < 8; i++) { t1 += red[i]; t2 += red[8 + i]; }
        red[16] = t1; red[17] = t2;
    }
    __syncthreads();
    float mean = red[16] * (1.f / HHD);
    float var  = red[17] * (1.f / HHD) - mean * mean;
    float rstd = rsqrtf(fmaxf(var, 0.f) + eps);

#pragma unroll
    for (int j = 0; j < 8; j++) {
        int g = base + j;
        v[j] = (v[j] - mean) * rstd * w[g] + bias[g];
    }

    if (do_rope) {
        int s = row % Smod;
        const float* fr = freqs + (size_t)s * (HD_ / 2) * 2;
#pragma unroll
        for (int jp = 0; jp < 4; jp++) {
            int g = base + 2 * jp;
            int pidx = (g & (HD_ - 1)) >> 1;
            float cs = fr[pidx * 2 + 0];
            float sn = fr[pidx * 2 + 1];
            float x0 = v[2 * jp], x1 = v[2 * jp + 1];
            v[2 * jp]     = x0 * cs - x1 * sn;
            v[2 * jp + 1] = x0 * sn + x1 * cs;
        }
    }

    uint2 hp, lp;
#pragma unroll
    for (int j = 0; j < 8; j++) {
        float x = v[j] * oscale;
        bf16 hh, ll;
        split_hl(x, hh, ll);
        ((bf16*)&hp)[j & 3] = hh;
        ((bf16*)&lp)[j & 3] = ll;
        if ((j & 3) == 3) {
            *(uint2*)(oh + (size_t)row * HHD + base + j - 3) = hp;
            *(uint2*)(ol + (size_t)row * HHD + base + j - 3) = lp;
        }
    }
}

// =====================================================================
// launch — serial single stream (R11 order; streams proven harmful)
// =====================================================================
extern "C" void kernel_launch(void* const* d_in, const int* in_sizes, int n_in,
                              void* d_out, int out_size)
{
    const float* x     = (const float*)d_in[0];
    const float* freqs = (const float*)d_in[2];
    const float* y     = (const float*)d_in[3];
    const float* wq    = (const float*)d_in[5];
    const float* wk    = (const float*)d_in[6];
    const float* wv    = (const float*)d_in[7];
    const float* wo    = (const float*)d_in[8];
    const float* wky   = (const float*)d_in[9];
    const float* wvy   = (const float*)d_in[10];
    const float* gate  = (const float*)d_in[11];
    const float* qn_w  = (const float*)d_in[12];
    const float* qn_b  = (const float*)d_in[13];
    const float* kn_w  = (const float*)d_in[14];
    const float* kn_b  = (const float*)d_in[15];
    const float* kyn_w = (const float*)d_in[16];
    const float* kyn_b = (const float*)d_in[17];
    float* out = (float*)d_out;

    float *q, *k, *v, *yk, *yv;
    bf16 *xh, *xl, *yh, *yl, *ath, *atl, *qh, *ql, *kh, *kl, *ykh, *ykl;
    fp16 *vth, *vtl, *yvth, *yvtl;
    bf16 *wqh, *wql, *wkh, *wkl, *wvh, *wvl, *woh, *wol, *wkyh, *wkyl, *wvyh, *wvyl;
    cudaGetSymbolAddress((void**)&q,    g_q);
    cudaGetSymbolAddress((void**)&k,    g_k);
    cudaGetSymbolAddress((void**)&v,    g_v);
    cudaGetSymbolAddress((void**)&yk,   g_yk);
    cudaGetSymbolAddress((void**)&yv,   g_yv);
    cudaGetSymbolAddress((void**)&xh,   g_xh);
    cudaGetSymbolAddress((void**)&xl,   g_xl);
    cudaGetSymbolAddress((void**)&yh,   g_yh);
    cudaGetSymbolAddress((void**)&yl,   g_yl);
    cudaGetSymbolAddress((void**)&ath,  g_ath);
    cudaGetSymbolAddress((void**)&atl,  g_atl);
    cudaGetSymbolAddress((void**)&qh,   g_qh);
    cudaGetSymbolAddress((void**)&ql,   g_ql);
    cudaGetSymbolAddress((void**)&kh,   g_kh);
    cudaGetSymbolAddress((void**)&kl,   g_kl);
    cudaGetSymbolAddress((void**)&ykh,  g_ykh);
    cudaGetSymbolAddress((void**)&ykl,  g_ykl);
    cudaGetSymbolAddress((void**)&vth,  g_vth);
    cudaGetSymbolAddress((void**)&vtl,  g_vtl);
    cudaGetSymbolAddress((void**)&yvth, g_yvth);
    cudaGetSymbolAddress((void**)&yvtl, g_yvtl);
    cudaGetSymbolAddress((void**)&wqh,  g_wqh);  cudaGetSymbolAddress((void**)&wql,  g_wql);
    cudaGetSymbolAddress((void**)&wkh,  g_wkh);  cudaGetSymbolAddress((void**)&wkl,  g_wkl);
    cudaGetSymbolAddress((void**)&wvh,  g_wvh);  cudaGetSymbolAddress((void**)&wvl,  g_wvl);
    cudaGetSymbolAddress((void**)&woh,  g_woh);  cudaGetSymbolAddress((void**)&wol,  g_wol);
    cudaGetSymbolAddress((void**)&wkyh, g_wkyh); cudaGetSymbolAddress((void**)&wkyl, g_wkyl);
    cudaGetSymbolAddress((void**)&wvyh, g_wvyh); cudaGetSymbolAddress((void**)&wvyl, g_wvyl);

    const int Mx = B_ * S_;    // 4096
    const int My = B_ * LY_;   // 1024

    // weights: transpose + split (vectorized)
    dim3 tg(64, 64), tb(32, 8);
    transpose_split_kernel<<<tg, tb>>>(wq,  wqh,  wql);
    transpose_split_kernel<<<tg, tb>>>(wk,  wkh,  wkl);
    transpose_split_kernel<<<tg, tb>>>(wv,  wvh,  wvl);
    transpose_split_kernel<<<tg, tb>>>(wo,  woh,  wol);
    transpose_split_kernel<<<tg, tb>>>(wky, wkyh, wkyl);
    transpose_split_kernel<<<tg, tb>>>(wvy, wvyh, wvyl);

    // activations split
    split_kernel<<<(Mx * D_ / 4 + 255) / 256, 256>>>(x, xh, xl, Mx * D_);
    split_kernel<<<(My * DY_ / 4 + 255) / 256, 256>>>(y, yh, yl, My * DY_);

    // tcgen05 bf16x3 GEMMs (serial, per-weight)
    cudaFuncSetAttribute(bf16x3_gemm_kernel,
                         cudaFuncAttributeMaxDynamicSharedMemorySize, GSMEM);
    dim3 gx(HHD / GBN, Mx / GBM);
    dim3 gy(HHD / GBN, My / GBM);
    bf16x3_gemm_kernel<<<gx, 256, GSMEM>>>(xh, xl, wqh,  wql,  q,  Mx, HHD, D_);
    bf16x3_gemm_kernel<<<gx, 256, GSMEM>>>(xh, xl, wkh,  wkl,  k,  Mx, HHD, D_);
    bf16x3_gemm_kernel<<<gx, 256, GSMEM>>>(xh, xl, wvh,  wvl,  v,  Mx, HHD, D_);
    bf16x3_gemm_kernel<<<gy, 256, GSMEM>>>(yh, yl, wkyh, wkyl, yk, My, HHD, DY_);
    bf16x3_gemm_kernel<<<gy, 256, GSMEM>>>(yh, yl, wvyh, wvyl, yv, My, HHD, DY_);

    // LayerNorm (+RoPE) -> bf16 hi/lo. Attention scale folded into q.
    const float scale = 0.08838834764831845f;
    ln_rope_split_kernel<<<Mx, 256>>>(q,  qn_w,  qn_b,  freqs, S_, 1e-5f, scale, 1, qh,  ql);
    ln_rope_split_kernel<<<Mx, 256>>>(k,  kn_w,  kn_b,  freqs, S_, 1e-5f, 1.f,   1, kh,  kl);
    ln_rope_split_kernel<<<My, 256>>>(yk, kyn_w, kyn_b, freqs, 1,  1e-6f, 1.f,   0, ykh, ykl);

    // V: transpose + fp16 hi/lo split (vectorized)
    vtrans_split_kernel<<<dim3(S_ / 32, HD_ / 32, B_ * H_), dim3(32, 8)>>>(v,  vth,  vtl,  S_);
    vtrans_split_kernel<<<dim3(LY_ / 32, HD_ / 32, B_ * H_), dim3(32, 8)>>>(yv, yvth, yvtl, LY_);

    // fused pipelined tcgen05 flash attention (8-warp softmax)
    cudaFuncSetAttribute(fattn_kernel,
                         cudaFuncAttributeMaxDynamicSharedMemorySize, AT_SMEM);
    fattn_kernel<<<dim3(S_ / 128, H_, B_), 256, AT_SMEM>>>(
        qh, ql, kh, kl, vth, vtl, ykh, ykl, yvth, yvtl, gate, ath, atl);

    // output projection
    bf16x3_gemm_kernel<<<dim3(D_ / GBN, Mx / GBM), 256, GSMEM>>>(
        ath, atl, woh, wol, out, Mx, D_, HHD);
}